// round 6
// baseline (speedup 1.0000x reference)
#include <cuda_runtime.h>
#include <cuda_fp16.h>

#define NN 10000
#define TT 50
#define Bn 2
#define Hn 64
#define BH 128          // Bn*Hn
#define IND 128         // input feature dim
#define EMAX 160000
#define CHUNK 8         // nodes per block in step kernel (1 node per warp)

// ---------------- device scratch (no allocation allowed) ----------------
__device__ float  d_h[2][NN * BH];          // double-buffered fp32 hidden state [node][b*H+h]
__device__ __half d_hh[2][NN * BH];         // fp16 mirror for the gather path
__device__ int    d_deg_in[NN];
__device__ int    d_deg_out[NN];
__device__ float  d_norm_s[NN];
__device__ float  d_norm_d[NN];
__device__ int    d_row_ptr[NN + 1];
__device__ int    d_fill_ptr[NN];
__device__ int2   d_csr[EMAX];              // (src, weight-as-int-bits)
__device__ float  d_xproj[3 * BH];          // [r|z|h][b][j]

// ---------------- precompute kernels ----------------
__global__ void init_kernel() {
    int i0 = blockIdx.x * blockDim.x + threadIdx.x;
    int stride = gridDim.x * blockDim.x;
    float4 z4 = make_float4(0.f, 0.f, 0.f, 0.f);
    float4* h0 = (float4*)d_h[0];
    for (int i = i0; i < NN * BH / 4; i += stride) h0[i] = z4;
    uint4* hh0 = (uint4*)d_hh[0];
    uint4 zu = make_uint4(0u, 0u, 0u, 0u);
    for (int i = i0; i < NN * BH / 8; i += stride) hh0[i] = zu;
    for (int i = i0; i < NN; i += stride) { d_deg_in[i] = 0; d_deg_out[i] = 0; }
}

__global__ void hist_kernel(const int* __restrict__ src, const int* __restrict__ dst, int E) {
    int e = blockIdx.x * blockDim.x + threadIdx.x;
    if (e < E) {
        atomicAdd(&d_deg_out[src[e]], 1);
        atomicAdd(&d_deg_in[dst[e]], 1);
    }
}

__global__ void norm_kernel() {
    int i = blockIdx.x * blockDim.x + threadIdx.x;
    if (i < NN) {
        d_norm_s[i] = rsqrtf((float)max(d_deg_out[i], 1));
        d_norm_d[i] = rsqrtf((float)max(d_deg_in[i], 1));
    }
}

// fast single-block exclusive scan: 10 elems/thread in regs + 2-level warp scan
__global__ void scan_kernel() {
    __shared__ int wsum[32];
    int tid = threadIdx.x;                 // 1024 threads
    const int PER = (NN + 1023) / 1024;    // 10
    int base = tid * PER;
    int loc[PER];
    int s = 0;
    #pragma unroll
    for (int k = 0; k < PER; k++) {
        int i = base + k;
        int v = (i < NN) ? d_deg_in[i] : 0;
        loc[k] = s; s += v;
    }
    int lane = tid & 31, w = tid >> 5;
    int ps = s;
    #pragma unroll
    for (int off = 1; off < 32; off <<= 1) {
        int t = __shfl_up_sync(0xffffffffu, ps, off);
        if (lane >= off) ps += t;
    }
    if (lane == 31) wsum[w] = ps;
    __syncthreads();
    if (w == 0) {
        int v = wsum[lane];
        #pragma unroll
        for (int off = 1; off < 32; off <<= 1) {
            int t = __shfl_up_sync(0xffffffffu, v, off);
            if (lane >= off) v += t;
        }
        wsum[lane] = v;
    }
    __syncthreads();
    int warpoff = (w == 0) ? 0 : wsum[w - 1];
    int excl = warpoff + ps - s;           // exclusive prefix of this thread's block
    #pragma unroll
    for (int k = 0; k < PER; k++) {
        int i = base + k;
        if (i < NN) {
            int rp = excl + loc[k];
            d_row_ptr[i] = rp;
            d_fill_ptr[i] = rp;
        }
    }
    if (tid == 1023) d_row_ptr[NN] = wsum[31];
}

__global__ void scatter_kernel(const int* __restrict__ src, const int* __restrict__ dst, int E) {
    int e = blockIdx.x * blockDim.x + threadIdx.x;
    if (e < E) {
        int s = src[e], d = dst[e];
        int pos = atomicAdd(&d_fill_ptr[d], 1);
        float w = d_norm_d[d] * d_norm_s[s];
        d_csr[pos] = make_int2(s, __float_as_int(w));
    }
}

// time-invariant input projections: xproj[p][b][j] = x[b] @ W_p + b_p
__global__ void xproj_kernel(const float* __restrict__ x,
                             const float* __restrict__ wr, const float* __restrict__ br,
                             const float* __restrict__ wz, const float* __restrict__ bz,
                             const float* __restrict__ wh, const float* __restrict__ bh) {
    __shared__ float xs[Bn * IND];
    int tid = threadIdx.x;
    if (tid < Bn * IND) xs[tid] = x[tid];
    __syncthreads();
    if (tid < 3 * BH) {
        int p = tid / BH, r = tid % BH, b = r / Hn, j = r % Hn;
        const float* W    = (p == 0) ? wr : (p == 1) ? wz : wh;
        const float* bias = (p == 0) ? br : (p == 1) ? bz : bh;
        float s = bias[j];
        #pragma unroll 8
        for (int k = 0; k < IND; k++)
            s += xs[b * IND + k] * W[k * Hn + j];
        d_xproj[tid] = s;
    }
}

__device__ __forceinline__ float4 h4_to_f4(uint2 v) {
    __half2 a = *(__half2*)&v.x;
    __half2 b = *(__half2*)&v.y;
    float2 fa = __half22float2(a);
    float2 fb = __half22float2(b);
    return make_float4(fa.x, fa.y, fb.x, fb.y);
}

__device__ __forceinline__ void fma4(float4& acc, float w, float4 v) {
    acc.x = fmaf(w, v.x, acc.x);
    acc.y = fmaf(w, v.y, acc.y);
    acc.z = fmaf(w, v.z, acc.z);
    acc.w = fmaf(w, v.w, acc.w);
}

// ---------------- fused GCN-GRU timestep ----------------
// phase 1: warp-per-node CSR gather-reduce (fp16 messages, MLP-4 unroll) into smem
// phase 2: channel-per-thread matvec (W column in registers), gates, state update, output
__global__ __launch_bounds__(256, 2) void step_kernel(
    const float* __restrict__ gcn_w, const float* __restrict__ gcn_b,
    float* __restrict__ out, int t) {
    __shared__ __align__(16) float agg_s[CHUNK * BH];
    __shared__ float xg_s[3 * BH];

    const float*  __restrict__ h_prev  = d_h[t & 1];
    float*        __restrict__ h_next  = d_h[(t & 1) ^ 1];
    const __half* __restrict__ hh_prev = d_hh[t & 1];
    __half*       __restrict__ hh_next = d_hh[(t & 1) ^ 1];

    for (int i = threadIdx.x; i < 3 * BH; i += 256) xg_s[i] = d_xproj[i];

    int warp = threadIdx.x >> 5, lane = threadIdx.x & 31;
    int node0 = blockIdx.x * CHUNK;

    // ---- phase 1: aggregation (1 node per warp) ----
    {
        int node = node0 + warp;
        int beg = __ldg(&d_row_ptr[node]), end = __ldg(&d_row_ptr[node + 1]);
        int lane4 = lane * 4;
        float4 acc = make_float4(0.f, 0.f, 0.f, 0.f);
        int p = beg;
        for (; p + 4 <= end; p += 4) {
            int2 e0 = __ldg(&d_csr[p]);
            int2 e1 = __ldg(&d_csr[p + 1]);
            int2 e2 = __ldg(&d_csr[p + 2]);
            int2 e3 = __ldg(&d_csr[p + 3]);
            uint2 v0 = *(const uint2*)&hh_prev[e0.x * BH + lane4];
            uint2 v1 = *(const uint2*)&hh_prev[e1.x * BH + lane4];
            uint2 v2 = *(const uint2*)&hh_prev[e2.x * BH + lane4];
            uint2 v3 = *(const uint2*)&hh_prev[e3.x * BH + lane4];
            fma4(acc, __int_as_float(e0.y), h4_to_f4(v0));
            fma4(acc, __int_as_float(e1.y), h4_to_f4(v1));
            fma4(acc, __int_as_float(e2.y), h4_to_f4(v2));
            fma4(acc, __int_as_float(e3.y), h4_to_f4(v3));
        }
        for (; p < end; p++) {
            int2 e = __ldg(&d_csr[p]);
            uint2 v = *(const uint2*)&hh_prev[e.x * BH + lane4];
            fma4(acc, __int_as_float(e.y), h4_to_f4(v));
        }
        *(float4*)&agg_s[warp * BH + lane4] = acc;
    }
    __syncthreads();

    // ---- phase 2: g = agg @ W + b, gates, update ----
    int j  = threadIdx.x & 63;   // output channel
    int pg = threadIdx.x >> 6;   // group 0..3
    float Wreg[64];
    #pragma unroll
    for (int k = 0; k < 64; k++) Wreg[k] = gcn_w[k * 64 + j];
    float bias_j = gcn_b[j];

    #pragma unroll
    for (int pi = pg; pi < CHUNK * 2; pi += 4) {
        int ln = pi >> 1, b = pi & 1;
        int node = node0 + ln;
        const float* a = &agg_s[ln * BH + b * Hn];
        float g = bias_j;
        #pragma unroll
        for (int k = 0; k < 64; k += 4) {
            float4 av = *(const float4*)&a[k];
            g = fmaf(av.x, Wreg[k],     g);
            g = fmaf(av.y, Wreg[k + 1], g);
            g = fmaf(av.z, Wreg[k + 2], g);
            g = fmaf(av.w, Wreg[k + 3], g);
        }
        int bj = b * Hn + j;
        float r = __fdividef(1.f, 1.f + __expf(-(xg_s[bj] + g)));
        float z = __fdividef(1.f, 1.f + __expf(-(xg_s[BH + bj] + g)));
        float targ = xg_s[2 * BH + bj] + r * g;
        float ht = __fdividef(2.f, 1.f + __expf(-2.f * targ)) - 1.f;   // tanh
        float hold = h_prev[node * BH + bj];
        float hn = (1.f - z) * hold + z * ht;
        h_next[node * BH + bj] = hn;
        hh_next[node * BH + bj] = __float2half_rn(hn);
        out[((size_t)(b * TT + t) * NN + node) * Hn + j] = hn;
    }
}

// ---------------- launch ----------------
extern "C" void kernel_launch(void* const* d_in, const int* in_sizes, int n_in,
                              void* d_out, int out_size) {
    const float* x    = (const float*)d_in[0];
    const int*   src  = (const int*)  d_in[1];
    const int*   dst  = (const int*)  d_in[2];
    const float* wr   = (const float*)d_in[3];
    const float* br   = (const float*)d_in[4];
    const float* wz   = (const float*)d_in[5];
    const float* bz   = (const float*)d_in[6];
    const float* wh   = (const float*)d_in[7];
    const float* bh   = (const float*)d_in[8];
    const float* gw   = (const float*)d_in[9];
    const float* gb   = (const float*)d_in[10];
    float* out = (float*)d_out;
    int E = in_sizes[1];

    init_kernel<<<256, 256>>>();
    hist_kernel<<<(E + 255) / 256, 256>>>(src, dst, E);
    norm_kernel<<<(NN + 255) / 256, 256>>>();
    scan_kernel<<<1, 1024>>>();
    scatter_kernel<<<(E + 255) / 256, 256>>>(src, dst, E);
    xproj_kernel<<<1, 512>>>(x, wr, br, wz, bz, wh, bh);

    for (int t = 0; t < TT; t++) {
        step_kernel<<<NN / CHUNK, 256>>>(gw, gb, out, t);
    }
}

// round 8
// speedup vs baseline: 1.0741x; 1.0741x over previous
#include <cuda_runtime.h>
#include <cuda_fp16.h>

#define NN 10000
#define TT 50
#define Bn 2
#define Hn 64
#define BH 128          // Bn*Hn
#define IND 128         // input feature dim
#define EMAX 160000
#define GRID 296        // 148 SMs x 2 blocks -- guaranteed co-resident
#define NPB 34          // nodes per block: 296*34 = 10064 >= 10000

// ---------------- device scratch (no allocation allowed) ----------------
__device__ float  d_h[2][NN * BH];          // double-buffered fp32 hidden state [node][b*H+h]
__device__ __half d_hh[2][NN * BH];         // fp16 mirror for the gather path
__device__ int    d_deg_in[NN];
__device__ int    d_deg_out[NN];
__device__ float  d_norm_s[NN];
__device__ float  d_norm_d[NN];
__device__ int    d_row_ptr[NN + 1];
__device__ int    d_fill_ptr[NN];
__device__ int2   d_csr[EMAX];              // (src, weight-as-int-bits)
__device__ float  d_xproj[3 * BH];          // [r|z|h][b][j]
__device__ int    g_bar;                    // global barrier arrivals
__device__ int    g_gen;                    // global barrier generation

// ---------------- precompute kernels ----------------
__global__ void init_kernel() {
    int i0 = blockIdx.x * blockDim.x + threadIdx.x;
    int stride = gridDim.x * blockDim.x;
    float4 z4 = make_float4(0.f, 0.f, 0.f, 0.f);
    float4* h0 = (float4*)d_h[0];
    for (int i = i0; i < NN * BH / 4; i += stride) h0[i] = z4;
    uint4* hh0 = (uint4*)d_hh[0];
    uint4 zu = make_uint4(0u, 0u, 0u, 0u);
    for (int i = i0; i < NN * BH / 8; i += stride) hh0[i] = zu;
    for (int i = i0; i < NN; i += stride) { d_deg_in[i] = 0; d_deg_out[i] = 0; }
    if (i0 == 0) { g_bar = 0; }
}

__global__ void hist_kernel(const int* __restrict__ src, const int* __restrict__ dst, int E) {
    int e = blockIdx.x * blockDim.x + threadIdx.x;
    if (e < E) {
        atomicAdd(&d_deg_out[src[e]], 1);
        atomicAdd(&d_deg_in[dst[e]], 1);
    }
}

// norms + fast single-block exclusive scan (reg-local + 2-level warp scan)
__global__ void scan_kernel() {
    __shared__ int wsum[32];
    int tid = threadIdx.x;                 // 1024 threads
    for (int i = tid; i < NN; i += 1024) {
        d_norm_s[i] = rsqrtf((float)max(d_deg_out[i], 1));
        d_norm_d[i] = rsqrtf((float)max(d_deg_in[i], 1));
    }
    const int PER = (NN + 1023) / 1024;    // 10
    int base = tid * PER;
    int loc[PER];
    int s = 0;
    #pragma unroll
    for (int k = 0; k < PER; k++) {
        int i = base + k;
        int v = (i < NN) ? d_deg_in[i] : 0;
        loc[k] = s; s += v;
    }
    int lane = tid & 31, w = tid >> 5;
    int ps = s;
    #pragma unroll
    for (int off = 1; off < 32; off <<= 1) {
        int t = __shfl_up_sync(0xffffffffu, ps, off);
        if (lane >= off) ps += t;
    }
    if (lane == 31) wsum[w] = ps;
    __syncthreads();
    if (w == 0) {
        int v = wsum[lane];
        #pragma unroll
        for (int off = 1; off < 32; off <<= 1) {
            int t = __shfl_up_sync(0xffffffffu, v, off);
            if (lane >= off) v += t;
        }
        wsum[lane] = v;
    }
    __syncthreads();
    int warpoff = (w == 0) ? 0 : wsum[w - 1];
    int excl = warpoff + ps - s;           // exclusive prefix of this thread's chunk
    #pragma unroll
    for (int k = 0; k < PER; k++) {
        int i = base + k;
        if (i < NN) {
            int rp = excl + loc[k];
            d_row_ptr[i] = rp;
            d_fill_ptr[i] = rp;
        }
    }
    if (tid == 1023) d_row_ptr[NN] = wsum[31];
}

__global__ void scatter_kernel(const int* __restrict__ src, const int* __restrict__ dst, int E) {
    int e = blockIdx.x * blockDim.x + threadIdx.x;
    if (e < E) {
        int s = src[e], d = dst[e];
        int pos = atomicAdd(&d_fill_ptr[d], 1);
        float w = d_norm_d[d] * d_norm_s[s];
        d_csr[pos] = make_int2(s, __float_as_int(w));
    }
}

// time-invariant input projections: xproj[p][b][j] = x[b] @ W_p + b_p
__global__ void xproj_kernel(const float* __restrict__ x,
                             const float* __restrict__ wr, const float* __restrict__ br,
                             const float* __restrict__ wz, const float* __restrict__ bz,
                             const float* __restrict__ wh, const float* __restrict__ bh) {
    __shared__ float xs[Bn * IND];
    int tid = threadIdx.x;
    if (tid < Bn * IND) xs[tid] = x[tid];
    __syncthreads();
    if (tid < 3 * BH) {
        int p = tid / BH, r = tid % BH, b = r / Hn, j = r % Hn;
        const float* W    = (p == 0) ? wr : (p == 1) ? wz : wh;
        const float* bias = (p == 0) ? br : (p == 1) ? bz : bh;
        float s = bias[j];
        #pragma unroll 8
        for (int k = 0; k < IND; k++)
            s += xs[b * IND + k] * W[k * Hn + j];
        d_xproj[tid] = s;
    }
}

__device__ __forceinline__ float4 h4_to_f4(uint2 v) {
    __half2 a = *(__half2*)&v.x;
    __half2 b = *(__half2*)&v.y;
    float2 fa = __half22float2(a);
    float2 fb = __half22float2(b);
    return make_float4(fa.x, fa.y, fb.x, fb.y);
}

__device__ __forceinline__ void fma4(float4& acc, float w, float4 v) {
    acc.x = fmaf(w, v.x, acc.x);
    acc.y = fmaf(w, v.y, acc.y);
    acc.z = fmaf(w, v.z, acc.z);
    acc.w = fmaf(w, v.w, acc.w);
}

// sense-reversing grid-wide barrier (all GRID blocks are co-resident)
__device__ __forceinline__ void grid_barrier() {
    __syncthreads();
    if (threadIdx.x == 0) {
        __threadfence();                       // publish this block's writes
        int gen = *(volatile int*)&g_gen;
        if (atomicAdd(&g_bar, 1) == GRID - 1) {
            g_bar = 0;
            __threadfence();
            atomicAdd(&g_gen, 1);
        } else {
            while (*(volatile int*)&g_gen == gen) { }
            __threadfence();                   // acquire
        }
    }
    __syncthreads();
}

// ---------------- persistent fused GCN-GRU: all 50 timesteps in one kernel ----------------
__global__ __launch_bounds__(256, 2) void persist_kernel(
    const float* __restrict__ gcn_w, const float* __restrict__ gcn_b,
    float* __restrict__ out) {
    __shared__ __align__(16) float agg_s[NPB * BH];
    __shared__ float xg_s[3 * BH];

    int tid = threadIdx.x;
    int warp = tid >> 5, lane = tid & 31;
    int node0 = blockIdx.x * NPB;
    int nb = NN - node0;
    if (nb > NPB) nb = NPB;
    if (nb < 0) nb = 0;

    for (int i = tid; i < 3 * BH; i += 256) xg_s[i] = d_xproj[i];

    // persistent per-thread weight column (loaded ONCE for all 50 steps)
    int j  = tid & 63;
    int pg = tid >> 6;
    float Wreg[64];
    #pragma unroll
    for (int k = 0; k < 64; k++) Wreg[k] = gcn_w[k * 64 + j];
    float bias_j = gcn_b[j];
    __syncthreads();

    for (int t = 0; t < TT; t++) {
        const float*  __restrict__ h_prev  = d_h[t & 1];
        float*        __restrict__ h_next  = d_h[(t & 1) ^ 1];
        const __half* __restrict__ hh_prev = d_hh[t & 1];
        __half*       __restrict__ hh_next = d_hh[(t & 1) ^ 1];

        // ---- phase 1: aggregation (1 node per warp per round) ----
        int lane4 = lane * 4;
        for (int ln = warp; ln < nb; ln += 8) {
            int node = node0 + ln;
            int beg = d_row_ptr[node], end = d_row_ptr[node + 1];
            float4 acc = make_float4(0.f, 0.f, 0.f, 0.f);
            int p = beg;
            for (; p + 4 <= end; p += 4) {
                int2 e0 = d_csr[p];
                int2 e1 = d_csr[p + 1];
                int2 e2 = d_csr[p + 2];
                int2 e3 = d_csr[p + 3];
                uint2 v0 = *(const uint2*)&hh_prev[e0.x * BH + lane4];
                uint2 v1 = *(const uint2*)&hh_prev[e1.x * BH + lane4];
                uint2 v2 = *(const uint2*)&hh_prev[e2.x * BH + lane4];
                uint2 v3 = *(const uint2*)&hh_prev[e3.x * BH + lane4];
                fma4(acc, __int_as_float(e0.y), h4_to_f4(v0));
                fma4(acc, __int_as_float(e1.y), h4_to_f4(v1));
                fma4(acc, __int_as_float(e2.y), h4_to_f4(v2));
                fma4(acc, __int_as_float(e3.y), h4_to_f4(v3));
            }
            for (; p < end; p++) {
                int2 e = d_csr[p];
                uint2 v = *(const uint2*)&hh_prev[e.x * BH + lane4];
                fma4(acc, __int_as_float(e.y), h4_to_f4(v));
            }
            *(float4*)&agg_s[ln * BH + lane4] = acc;
        }
        __syncthreads();

        // ---- phase 2: g = agg @ W + b, gates, state update, output ----
        for (int pi = pg; pi < nb * 2; pi += 4) {
            int ln = pi >> 1, b = pi & 1;
            int node = node0 + ln;
            const float* a = &agg_s[ln * BH + b * Hn];
            float g = bias_j;
            #pragma unroll
            for (int k = 0; k < 64; k += 4) {
                float4 av = *(const float4*)&a[k];   // warp-broadcast LDS
                g = fmaf(av.x, Wreg[k],     g);
                g = fmaf(av.y, Wreg[k + 1], g);
                g = fmaf(av.z, Wreg[k + 2], g);
                g = fmaf(av.w, Wreg[k + 3], g);
            }
            int bj = b * Hn + j;
            float r = __fdividef(1.f, 1.f + __expf(-(xg_s[bj] + g)));
            float z = __fdividef(1.f, 1.f + __expf(-(xg_s[BH + bj] + g)));
            float targ = xg_s[2 * BH + bj] + r * g;
            float ht = __fdividef(2.f, 1.f + __expf(-2.f * targ)) - 1.f;   // tanh
            float hold = h_prev[node * BH + bj];
            float hn = (1.f - z) * hold + z * ht;
            h_next[node * BH + bj] = hn;
            hh_next[node * BH + bj] = __float2half_rn(hn);
            out[((size_t)(b * TT + t) * NN + node) * Hn + j] = hn;
        }

        // ---- grid-wide sync before next timestep ----
        if (t < TT - 1) grid_barrier();
    }
}

// ---------------- launch ----------------
extern "C" void kernel_launch(void* const* d_in, const int* in_sizes, int n_in,
                              void* d_out, int out_size) {
    const float* x    = (const float*)d_in[0];
    const int*   src  = (const int*)  d_in[1];
    const int*   dst  = (const int*)  d_in[2];
    const float* wr   = (const float*)d_in[3];
    const float* br   = (const float*)d_in[4];
    const float* wz   = (const float*)d_in[5];
    const float* bz   = (const float*)d_in[6];
    const float* wh   = (const float*)d_in[7];
    const float* bh   = (const float*)d_in[8];
    const float* gw   = (const float*)d_in[9];
    const float* gb   = (const float*)d_in[10];
    float* out = (float*)d_out;
    int E = in_sizes[1];

    init_kernel<<<256, 256>>>();                       // launch 0
    hist_kernel<<<(E + 255) / 256, 256>>>(src, dst, E);// launch 1
    scan_kernel<<<1, 1024>>>();                        // launch 2 (norms + scan)
    scatter_kernel<<<(E + 255) / 256, 256>>>(src, dst, E); // launch 3
    xproj_kernel<<<1, 512>>>(x, wr, br, wz, bz, wh, bh);   // launch 4
    persist_kernel<<<GRID, 256>>>(gw, gb, out);        // launch 5 -> ncu -s 5 profiles this
}

// round 9
// speedup vs baseline: 1.0963x; 1.0206x over previous
#include <cuda_runtime.h>
#include <cuda_fp16.h>

#define NN 10000
#define TT 50
#define Bn 2
#define Hn 64
#define BH 128          // Bn*Hn
#define IND 128         // input feature dim
#define EMAX 160000
#define GRID 296        // 148 SMs x 2 blocks -- co-resident
#define NPB 34          // nodes per block: 296*34 = 10064 >= 10000

typedef unsigned long long u64;

// ---------------- device scratch (no allocation allowed) ----------------
__device__ float  d_h[2][NN * BH];          // double-buffered fp32 hidden state [node][b*H+h]
__device__ __half d_hh[2][NN * BH];         // fp16 mirror for the gather path
__device__ int    d_deg_in[NN];
__device__ int    d_deg_out[NN];
__device__ float  d_norm_s[NN];
__device__ float  d_norm_d[NN];
__device__ int    d_row_ptr[NN + 1];
__device__ int    d_fill_ptr[NN];
__device__ int2   d_csr[EMAX];              // (src, weight-as-int-bits)
__device__ float  d_xproj[3 * BH];          // [r|z|h][b][j]
__device__ int    g_bar;                    // global barrier arrivals
__device__ int    g_gen;                    // global barrier generation

// ---------------- packed f32x2 helpers (Blackwell FFMA2) ----------------
__device__ __forceinline__ u64 pack2(float lo, float hi) {
    u64 r; asm("mov.b64 %0, {%1, %2};" : "=l"(r) : "f"(lo), "f"(hi)); return r;
}
__device__ __forceinline__ void unpack2(u64 v, float& lo, float& hi) {
    asm("mov.b64 {%0, %1}, %2;" : "=f"(lo), "=f"(hi) : "l"(v));
}
__device__ __forceinline__ void ffma2(u64& d, u64 a, u64 b) {
    asm("fma.rn.f32x2 %0, %1, %2, %0;" : "+l"(d) : "l"(a), "l"(b));
}

// ---------------- precompute kernels ----------------
__global__ void init_kernel() {
    int i0 = blockIdx.x * blockDim.x + threadIdx.x;
    int stride = gridDim.x * blockDim.x;
    float4 z4 = make_float4(0.f, 0.f, 0.f, 0.f);
    float4* h0 = (float4*)d_h[0];
    for (int i = i0; i < NN * BH / 4; i += stride) h0[i] = z4;
    uint4* hh0 = (uint4*)d_hh[0];
    uint4 zu = make_uint4(0u, 0u, 0u, 0u);
    for (int i = i0; i < NN * BH / 8; i += stride) hh0[i] = zu;
    for (int i = i0; i < NN; i += stride) { d_deg_in[i] = 0; d_deg_out[i] = 0; }
    if (i0 == 0) { g_bar = 0; }
}

__global__ void hist_kernel(const int* __restrict__ src, const int* __restrict__ dst, int E) {
    int e = blockIdx.x * blockDim.x + threadIdx.x;
    if (e < E) {
        atomicAdd(&d_deg_out[src[e]], 1);
        atomicAdd(&d_deg_in[dst[e]], 1);
    }
}

// norms + fast single-block exclusive scan (reg-local + 2-level warp scan)
__global__ void scan_kernel() {
    __shared__ int wsum[32];
    int tid = threadIdx.x;                 // 1024 threads
    for (int i = tid; i < NN; i += 1024) {
        d_norm_s[i] = rsqrtf((float)max(d_deg_out[i], 1));
        d_norm_d[i] = rsqrtf((float)max(d_deg_in[i], 1));
    }
    const int PER = (NN + 1023) / 1024;    // 10
    int base = tid * PER;
    int loc[PER];
    int s = 0;
    #pragma unroll
    for (int k = 0; k < PER; k++) {
        int i = base + k;
        int v = (i < NN) ? d_deg_in[i] : 0;
        loc[k] = s; s += v;
    }
    int lane = tid & 31, w = tid >> 5;
    int ps = s;
    #pragma unroll
    for (int off = 1; off < 32; off <<= 1) {
        int t = __shfl_up_sync(0xffffffffu, ps, off);
        if (lane >= off) ps += t;
    }
    if (lane == 31) wsum[w] = ps;
    __syncthreads();
    if (w == 0) {
        int v = wsum[lane];
        #pragma unroll
        for (int off = 1; off < 32; off <<= 1) {
            int t = __shfl_up_sync(0xffffffffu, v, off);
            if (lane >= off) v += t;
        }
        wsum[lane] = v;
    }
    __syncthreads();
    int warpoff = (w == 0) ? 0 : wsum[w - 1];
    int excl = warpoff + ps - s;
    #pragma unroll
    for (int k = 0; k < PER; k++) {
        int i = base + k;
        if (i < NN) {
            int rp = excl + loc[k];
            d_row_ptr[i] = rp;
            d_fill_ptr[i] = rp;
        }
    }
    if (tid == 1023) d_row_ptr[NN] = wsum[31];
}

__global__ void scatter_kernel(const int* __restrict__ src, const int* __restrict__ dst, int E) {
    int e = blockIdx.x * blockDim.x + threadIdx.x;
    if (e < E) {
        int s = src[e], d = dst[e];
        int pos = atomicAdd(&d_fill_ptr[d], 1);
        float w = d_norm_d[d] * d_norm_s[s];
        d_csr[pos] = make_int2(s, __float_as_int(w));
    }
}

// time-invariant input projections: xproj[p][b][j] = x[b] @ W_p + b_p
__global__ void xproj_kernel(const float* __restrict__ x,
                             const float* __restrict__ wr, const float* __restrict__ br,
                             const float* __restrict__ wz, const float* __restrict__ bz,
                             const float* __restrict__ wh, const float* __restrict__ bh) {
    __shared__ float xs[Bn * IND];
    int tid = threadIdx.x;
    if (tid < Bn * IND) xs[tid] = x[tid];
    __syncthreads();
    if (tid < 3 * BH) {
        int p = tid / BH, r = tid % BH, b = r / Hn, j = r % Hn;
        const float* W    = (p == 0) ? wr : (p == 1) ? wz : wh;
        const float* bias = (p == 0) ? br : (p == 1) ? bz : bh;
        float s = bias[j];
        #pragma unroll 8
        for (int k = 0; k < IND; k++)
            s += xs[b * IND + k] * W[k * Hn + j];
        d_xproj[tid] = s;
    }
}

// accumulate one fp16 message (uint2 = 4 halves) with packed FFMA2
__device__ __forceinline__ void acc_msg(u64& a01, u64& a23, u64 ww, uint2 v) {
    float2 fa = __half22float2(*(__half2*)&v.x);
    float2 fb = __half22float2(*(__half2*)&v.y);
    ffma2(a01, ww, pack2(fa.x, fa.y));
    ffma2(a23, ww, pack2(fb.x, fb.y));
}

// drain remaining edges of one stream (MLP-4)
__device__ __forceinline__ void gather_tail(int p, int end, int lane4,
                                            const __half* __restrict__ hh,
                                            u64& a01, u64& a23) {
    for (; p + 4 <= end; p += 4) {
        int2 e0 = __ldg(&d_csr[p]);
        int2 e1 = __ldg(&d_csr[p + 1]);
        int2 e2 = __ldg(&d_csr[p + 2]);
        int2 e3 = __ldg(&d_csr[p + 3]);
        uint2 v0 = __ldcg((const uint2*)&hh[e0.x * BH + lane4]);
        uint2 v1 = __ldcg((const uint2*)&hh[e1.x * BH + lane4]);
        uint2 v2 = __ldcg((const uint2*)&hh[e2.x * BH + lane4]);
        uint2 v3 = __ldcg((const uint2*)&hh[e3.x * BH + lane4]);
        acc_msg(a01, a23, pack2(__int_as_float(e0.y), __int_as_float(e0.y)), v0);
        acc_msg(a01, a23, pack2(__int_as_float(e1.y), __int_as_float(e1.y)), v1);
        acc_msg(a01, a23, pack2(__int_as_float(e2.y), __int_as_float(e2.y)), v2);
        acc_msg(a01, a23, pack2(__int_as_float(e3.y), __int_as_float(e3.y)), v3);
    }
    for (; p < end; p++) {
        int2 e = __ldg(&d_csr[p]);
        uint2 v = __ldcg((const uint2*)&hh[e.x * BH + lane4]);
        acc_msg(a01, a23, pack2(__int_as_float(e.y), __int_as_float(e.y)), v);
    }
}

// sense-reversing grid-wide barrier (all GRID blocks co-resident)
__device__ __forceinline__ void grid_barrier() {
    __syncthreads();
    if (threadIdx.x == 0) {
        __threadfence();
        int gen = *(volatile int*)&g_gen;
        if (atomicAdd(&g_bar, 1) == GRID - 1) {
            g_bar = 0;
            __threadfence();
            atomicAdd(&g_gen, 1);
        } else {
            while (*(volatile int*)&g_gen == gen) { }
            __threadfence();
        }
    }
    __syncthreads();
}

// ---------------- persistent fused GCN-GRU: all 50 timesteps in one kernel ----------------
__global__ __launch_bounds__(256, 2) void persist_kernel(
    const float* __restrict__ gcn_w, const float* __restrict__ gcn_b,
    float* __restrict__ out) {
    __shared__ __align__(16) float agg_s[NPB * BH];
    __shared__ float xg_s[3 * BH];

    int tid = threadIdx.x;
    int warp = tid >> 5, lane = tid & 31;
    int node0 = blockIdx.x * NPB;
    int nb = NN - node0;
    if (nb > NPB) nb = NPB;
    if (nb < 0) nb = 0;

    for (int i = tid; i < 3 * BH; i += 256) xg_s[i] = d_xproj[i];

    // persistent per-thread weight column, packed into f32x2 pairs over k
    int j  = tid & 63;
    int pg = tid >> 6;
    u64 Wp[32];
    #pragma unroll
    for (int k = 0; k < 32; k++)
        Wp[k] = pack2(gcn_w[(2 * k) * 64 + j], gcn_w[(2 * k + 1) * 64 + j]);
    float bias_j = gcn_b[j];
    __syncthreads();

    for (int t = 0; t < TT; t++) {
        const float*  __restrict__ h_prev  = d_h[t & 1];
        float*        __restrict__ h_next  = d_h[(t & 1) ^ 1];
        const __half* __restrict__ hh_prev = d_hh[t & 1];
        __half*       __restrict__ hh_next = d_hh[(t & 1) ^ 1];

        // ---- phase 1: dual-stream gather (2 nodes per warp, 4 msg loads in flight) ----
        int lane4 = lane * 4;
        for (int base = 0; base < nb; base += 16) {
            int lnA = base + warp;
            int lnB = base + warp + 8;
            bool actA = lnA < nb, actB = lnB < nb;
            int pA = 0, eA = 0, pB = 0, eB = 0;
            if (actA) { pA = __ldg(&d_row_ptr[node0 + lnA]); eA = __ldg(&d_row_ptr[node0 + lnA + 1]); }
            if (actB) { pB = __ldg(&d_row_ptr[node0 + lnB]); eB = __ldg(&d_row_ptr[node0 + lnB + 1]); }
            u64 a01 = 0, a23 = 0, b01 = 0, b23 = 0;

            while (pA + 2 <= eA && pB + 2 <= eB) {
                int2 ea0 = __ldg(&d_csr[pA]);
                int2 ea1 = __ldg(&d_csr[pA + 1]);
                int2 eb0 = __ldg(&d_csr[pB]);
                int2 eb1 = __ldg(&d_csr[pB + 1]);
                uint2 va0 = __ldcg((const uint2*)&hh_prev[ea0.x * BH + lane4]);
                uint2 va1 = __ldcg((const uint2*)&hh_prev[ea1.x * BH + lane4]);
                uint2 vb0 = __ldcg((const uint2*)&hh_prev[eb0.x * BH + lane4]);
                uint2 vb1 = __ldcg((const uint2*)&hh_prev[eb1.x * BH + lane4]);
                acc_msg(a01, a23, pack2(__int_as_float(ea0.y), __int_as_float(ea0.y)), va0);
                acc_msg(a01, a23, pack2(__int_as_float(ea1.y), __int_as_float(ea1.y)), va1);
                acc_msg(b01, b23, pack2(__int_as_float(eb0.y), __int_as_float(eb0.y)), vb0);
                acc_msg(b01, b23, pack2(__int_as_float(eb1.y), __int_as_float(eb1.y)), vb1);
                pA += 2; pB += 2;
            }
            if (actA) gather_tail(pA, eA, lane4, hh_prev, a01, a23);
            if (actB) gather_tail(pB, eB, lane4, hh_prev, b01, b23);

            if (actA) {
                float4 r;
                unpack2(a01, r.x, r.y); unpack2(a23, r.z, r.w);
                *(float4*)&agg_s[lnA * BH + lane4] = r;
            }
            if (actB) {
                float4 r;
                unpack2(b01, r.x, r.y); unpack2(b23, r.z, r.w);
                *(float4*)&agg_s[lnB * BH + lane4] = r;
            }
        }
        __syncthreads();

        // ---- phase 2: g = agg @ W + b (FFMA2), gates, state update, output ----
        for (int pi = pg; pi < nb * 2; pi += 4) {
            int ln = pi >> 1, b = pi & 1;
            int node = node0 + ln;
            const float* a = &agg_s[ln * BH + b * Hn];
            u64 g2 = 0;
            #pragma unroll
            for (int k = 0; k < 16; k++) {
                float4 av = *(const float4*)&a[k * 4];   // warp-broadcast LDS
                ffma2(g2, pack2(av.x, av.y), Wp[2 * k]);
                ffma2(g2, pack2(av.z, av.w), Wp[2 * k + 1]);
            }
            float glo, ghi;
            unpack2(g2, glo, ghi);
            float g = bias_j + glo + ghi;
            int bj = b * Hn + j;
            float r = __fdividef(1.f, 1.f + __expf(-(xg_s[bj] + g)));
            float z = __fdividef(1.f, 1.f + __expf(-(xg_s[BH + bj] + g)));
            float targ = xg_s[2 * BH + bj] + r * g;
            float ht = __fdividef(2.f, 1.f + __expf(-2.f * targ)) - 1.f;   // tanh
            float hold = __ldcg(&h_prev[node * BH + bj]);
            float hn = (1.f - z) * hold + z * ht;
            h_next[node * BH + bj] = hn;
            hh_next[node * BH + bj] = __float2half_rn(hn);
            out[((size_t)(b * TT + t) * NN + node) * Hn + j] = hn;
        }

        if (t < TT - 1) grid_barrier();
    }
}

// ---------------- launch ----------------
extern "C" void kernel_launch(void* const* d_in, const int* in_sizes, int n_in,
                              void* d_out, int out_size) {
    const float* x    = (const float*)d_in[0];
    const int*   src  = (const int*)  d_in[1];
    const int*   dst  = (const int*)  d_in[2];
    const float* wr   = (const float*)d_in[3];
    const float* br   = (const float*)d_in[4];
    const float* wz   = (const float*)d_in[5];
    const float* bz   = (const float*)d_in[6];
    const float* wh   = (const float*)d_in[7];
    const float* bh   = (const float*)d_in[8];
    const float* gw   = (const float*)d_in[9];
    const float* gb   = (const float*)d_in[10];
    float* out = (float*)d_out;
    int E = in_sizes[1];

    init_kernel<<<256, 256>>>();
    hist_kernel<<<(E + 255) / 256, 256>>>(src, dst, E);
    scan_kernel<<<1, 1024>>>();
    scatter_kernel<<<(E + 255) / 256, 256>>>(src, dst, E);
    xproj_kernel<<<1, 512>>>(x, wr, br, wz, bz, wh, bh);
    persist_kernel<<<GRID, 256>>>(gw, gb, out);
}